// round 14
// baseline (speedup 1.0000x reference)
#include <cuda_runtime.h>
#include <cuda_fp16.h>
#include <cstdint>
#include <cstddef>

// ---------------------------------------------------------------------------
// Problem constants (padded capacities for static scratch)
// ---------------------------------------------------------------------------
#define NMAX 50048
#define EMAX 1000064
#define H0 8
#define DOUT 32
#define F0DIM (H0*DOUT)     // 256

// ---------------------------------------------------------------------------
// Static device scratch
// ---------------------------------------------------------------------------
__device__ __half g_f16[(size_t)NMAX * F0DIM];   // layer-0 features (fp16)
__device__ float g_h0[(size_t)NMAX * F0DIM];     // layer-0 output (after elu)
__device__ float g_f1[(size_t)NMAX * DOUT];
__device__ float g_h1[(size_t)NMAX * DOUT];
__device__ float g_el0[(size_t)NMAX * H0];
__device__ float g_er0[(size_t)NMAX * H0];
__device__ float g_el1[NMAX];
__device__ float g_er1[NMAX];
__device__ int   g_cnt[NMAX];
__device__ int   g_rowptr[NMAX + 1];
__device__ int   g_cursor[NMAX];
__device__ int   g_csrc[EMAX];

// ---------------------------------------------------------------------------
// CSR build: hist -> scan -> fill (+ memset for counts)
// ---------------------------------------------------------------------------
__global__ void k_hist(const int* __restrict__ dst, int E) {
    int e = blockIdx.x * blockDim.x + threadIdx.x;
    if (e < E) atomicAdd(&g_cnt[dst[e]], 1);
}

__global__ void k_scan(int N) {
    __shared__ int s[1024];
    int t = threadIdx.x;
    int C = (N + 1023) / 1024;
    int beg = t * C;
    int end = beg + C; if (end > N) end = N;
    int sum = 0;
    for (int i = beg; i < end; i++) sum += g_cnt[i];
    s[t] = sum;
    __syncthreads();
    for (int off = 1; off < 1024; off <<= 1) {
        int u = (t >= off) ? s[t - off] : 0;
        __syncthreads();
        if (t >= off) s[t] += u;
        __syncthreads();
    }
    int pre = (t == 0) ? 0 : s[t - 1];
    for (int i = beg; i < end; i++) {
        int c = g_cnt[i];
        g_rowptr[i] = pre;
        g_cursor[i] = pre;
        pre += c;
    }
    if (t == 1023) g_rowptr[N] = s[1023];
}

__global__ void k_fill(const int* __restrict__ src, const int* __restrict__ dst, int E) {
    int e = blockIdx.x * blockDim.x + threadIdx.x;
    if (e < E) {
        int p = atomicAdd(&g_cursor[dst[e]], 1);
        g_csrc[p] = src[e];
    }
}

// ---------------------------------------------------------------------------
// TF32 tensor-core GEMM with fused attention-score epilogue.
// ---------------------------------------------------------------------------
__device__ __forceinline__ uint32_t f2tf32(float v) {
    uint32_t u;
    asm("cvt.rna.tf32.f32 %0, %1;" : "=r"(u) : "f"(v));
    return u;
}

template<int BN, int WMI, int WNI, bool HALF_OUT>
__global__ __launch_bounds__(256) void k_gemm_tf32(
    const float* __restrict__ A, const float* __restrict__ B,
    void* __restrict__ Cv,
    const float* __restrict__ al, const float* __restrict__ ar,
    float* __restrict__ el, float* __restrict__ er,
    int M, int N, int K, int H)
{
    constexpr int BM = 128;
    constexpr int BK = 32;
    constexpr int WM = BM / WMI;
    constexpr int WN = BN / WNI;
    constexpr int MFR = WM / 16;
    constexpr int NFR = WN / 8;
    constexpr int HW  = (WN + 31) / 32;
    constexpr int AS_STRIDE = 36;
    constexpr int BS_STRIDE = BN + 8;

    __shared__ uint32_t As[BM * AS_STRIDE];
    __shared__ uint32_t Bs[BK * BS_STRIDE];

    int tid = threadIdx.x;
    int lane = tid & 31;
    int w = tid >> 5;
    int warp_m = w % WMI;
    int warp_n = w / WMI;
    int m0 = blockIdx.y * BM;
    int n0 = blockIdx.x * BN;
    int wr = warp_m * WM;

    float c[MFR][NFR][4];
#pragma unroll
    for (int i = 0; i < MFR; i++)
#pragma unroll
        for (int j = 0; j < NFR; j++)
#pragma unroll
            for (int q = 0; q < 4; q++) c[i][j][q] = 0.f;

    for (int k0 = 0; k0 < K; k0 += BK) {
#pragma unroll
        for (int q = 0; q < (BM * BK / 4) / 256; q++) {
            int idx = tid + q * 256;
            int row = idx >> 3;
            int c4  = idx & 7;
            uint4 u = make_uint4(0u, 0u, 0u, 0u);
            int grow = m0 + row;
            if (grow < M) {
                float4 v = *(const float4*)(A + (size_t)grow * K + k0 + c4 * 4);
                u.x = f2tf32(v.x); u.y = f2tf32(v.y);
                u.z = f2tf32(v.z); u.w = f2tf32(v.w);
            }
            *(uint4*)&As[row * AS_STRIDE + c4 * 4] = u;
        }
#pragma unroll
        for (int q = 0; q < (BK * BN / 4) / 256; q++) {
            int idx = tid + q * 256;
            int row = idx / (BN / 4);
            int c4  = idx % (BN / 4);
            float4 v = *(const float4*)(B + (size_t)(k0 + row) * N + n0 + c4 * 4);
            uint4 u;
            u.x = f2tf32(v.x); u.y = f2tf32(v.y);
            u.z = f2tf32(v.z); u.w = f2tf32(v.w);
            *(uint4*)&Bs[row * BS_STRIDE + c4 * 4] = u;
        }
        __syncthreads();

#pragma unroll
        for (int kk = 0; kk < BK; kk += 8) {
            uint32_t af[MFR][4];
#pragma unroll
            for (int mf = 0; mf < MFR; mf++) {
                int r = wr + mf * 16 + (lane >> 2);
                int kc = kk + (lane & 3);
                af[mf][0] = As[r * AS_STRIDE + kc];
                af[mf][1] = As[(r + 8) * AS_STRIDE + kc];
                af[mf][2] = As[r * AS_STRIDE + kc + 4];
                af[mf][3] = As[(r + 8) * AS_STRIDE + kc + 4];
            }
            uint32_t bf[NFR][2];
#pragma unroll
            for (int nf = 0; nf < NFR; nf++) {
                int n = warp_n * WN + nf * 8 + (lane >> 2);
                int kc = kk + (lane & 3);
                bf[nf][0] = Bs[kc * BS_STRIDE + n];
                bf[nf][1] = Bs[(kc + 4) * BS_STRIDE + n];
            }
#pragma unroll
            for (int mf = 0; mf < MFR; mf++)
#pragma unroll
                for (int nf = 0; nf < NFR; nf++) {
                    asm volatile(
                        "mma.sync.aligned.m16n8k8.row.col.f32.tf32.tf32.f32 "
                        "{%0,%1,%2,%3}, {%4,%5,%6,%7}, {%8,%9}, {%0,%1,%2,%3};\n"
                        : "+f"(c[mf][nf][0]), "+f"(c[mf][nf][1]),
                          "+f"(c[mf][nf][2]), "+f"(c[mf][nf][3])
                        : "r"(af[mf][0]), "r"(af[mf][1]), "r"(af[mf][2]), "r"(af[mf][3]),
                          "r"(bf[nf][0]), "r"(bf[nf][1]));
                }
        }
        __syncthreads();
    }

    float elp[MFR][2][HW], erp[MFR][2][HW];
#pragma unroll
    for (int mf = 0; mf < MFR; mf++)
#pragma unroll
        for (int hf = 0; hf < 2; hf++)
#pragma unroll
            for (int hh = 0; hh < HW; hh++) { elp[mf][hf][hh] = 0.f; erp[mf][hf][hh] = 0.f; }

#pragma unroll
    for (int nf = 0; nf < NFR; nf++) {
        int colb = warp_n * WN + nf * 8;
        int hw = (nf * 8) >> 5;
        int hg = (n0 + colb) >> 5;
        int ch = (colb & 31) + 2 * (lane & 3);
        float av0 = al[hg * 32 + ch], av1 = al[hg * 32 + ch + 1];
        float rv0 = ar[hg * 32 + ch], rv1 = ar[hg * 32 + ch + 1];
        int gcol = n0 + colb + 2 * (lane & 3);
#pragma unroll
        for (int mf = 0; mf < MFR; mf++) {
            int r0 = m0 + wr + mf * 16 + (lane >> 2);
            int r1 = r0 + 8;
            float c0 = c[mf][nf][0], c1 = c[mf][nf][1];
            float c2 = c[mf][nf][2], c3 = c[mf][nf][3];
            if (HALF_OUT) {
                __half* C = (__half*)Cv;
                if (r0 < M) *(__half2*)(C + (size_t)r0 * N + gcol) = __floats2half2_rn(c0, c1);
                if (r1 < M) *(__half2*)(C + (size_t)r1 * N + gcol) = __floats2half2_rn(c2, c3);
            } else {
                float* C = (float*)Cv;
                if (r0 < M) *(float2*)(C + (size_t)r0 * N + gcol) = make_float2(c0, c1);
                if (r1 < M) *(float2*)(C + (size_t)r1 * N + gcol) = make_float2(c2, c3);
            }
            elp[mf][0][hw] += c0 * av0 + c1 * av1;
            elp[mf][1][hw] += c2 * av0 + c3 * av1;
            erp[mf][0][hw] += c0 * rv0 + c1 * rv1;
            erp[mf][1][hw] += c2 * rv0 + c3 * rv1;
        }
    }
#pragma unroll
    for (int mf = 0; mf < MFR; mf++)
#pragma unroll
        for (int hf = 0; hf < 2; hf++)
#pragma unroll
            for (int hh = 0; hh < HW; hh++) {
                float a = elp[mf][hf][hh], b = erp[mf][hf][hh];
                a += __shfl_xor_sync(0xffffffffu, a, 1);
                a += __shfl_xor_sync(0xffffffffu, a, 2);
                b += __shfl_xor_sync(0xffffffffu, b, 1);
                b += __shfl_xor_sync(0xffffffffu, b, 2);
                if ((lane & 3) == 0) {
                    int row = m0 + wr + mf * 16 + (lane >> 2) + hf * 8;
                    int hg = (n0 + warp_n * WN) / 32 + hh;
                    if (row < M) {
                        el[(size_t)row * H + hg] = a;
                        er[(size_t)row * H + hg] = b;
                    }
                }
            }
}

// ---------------------------------------------------------------------------
// Layer-0 aggregation, warp-per-edge (R9 base) + 2-way unrolled edge loop.
// Index staging, shfl/sred reduction, NO smem atomics (R12 lesson).
// ---------------------------------------------------------------------------
__global__ __launch_bounds__(128) void k_agg0(const __half* __restrict__ f16,
                                              const float* __restrict__ el,
                                              const float* __restrict__ er,
                                              const float* __restrict__ bias,
                                              float* __restrict__ out, int N) {
    __shared__ int   se[128];
    __shared__ float sw[128 * H0];
    __shared__ float ser[H0];
    __shared__ float sred[4][256];
    __shared__ float sden[4][H0];
    int i = blockIdx.x;
    if (i >= N) return;
    int t = threadIdx.x, lane = t & 31, wid = t >> 5;
    if (t < H0) ser[t] = er[i * H0 + t];
    int s0 = g_rowptr[i], s1 = g_rowptr[i + 1];
    int head = lane >> 2;
    const uint4* frow = (const uint4*)f16;
    const float* swp = &sw[head];           // per-warp-lane weight base

    float accA[8], accB[8];
#pragma unroll
    for (int q = 0; q < 8; q++) { accA[q] = 0.f; accB[q] = 0.f; }
    float denA = 0.f, denB = 0.f;

    for (int base = s0; base < s1; base += 128) {
        int cnt = min(128, s1 - base);
        __syncthreads();
        if (t < cnt) se[t] = g_csrc[base + t];
        __syncthreads();
        for (int idx = t; idx < cnt * H0; idx += 128) {
            int j = idx >> 3, h = idx & 7;
            float e = el[se[j] * H0 + h] + ser[h];
            e = (e > 0.f) ? e : 0.2f * e;
            sw[idx] = __expf(e);
        }
        __syncthreads();
        int j = wid;
        for (; j + 4 < cnt; j += 8) {
            int sA = se[j], sB = se[j + 4];
            float aA = swp[j * H0];
            float aB = swp[(j + 4) * H0];
            uint4 vA = frow[(size_t)sA * 32 + lane];
            uint4 vB = frow[(size_t)sB * 32 + lane];
            const __half2* hA = (const __half2*)&vA;
            const __half2* hB = (const __half2*)&vB;
#pragma unroll
            for (int q = 0; q < 4; q++) {
                float2 fA = __half22float2(hA[q]);
                float2 fB = __half22float2(hB[q]);
                accA[2 * q]     += aA * fA.x;
                accA[2 * q + 1] += aA * fA.y;
                accB[2 * q]     += aB * fB.x;
                accB[2 * q + 1] += aB * fB.y;
            }
            denA += aA;
            denB += aB;
        }
        if (j < cnt) {
            int sA = se[j];
            float aA = swp[j * H0];
            uint4 vA = frow[(size_t)sA * 32 + lane];
            const __half2* hA = (const __half2*)&vA;
#pragma unroll
            for (int q = 0; q < 4; q++) {
                float2 fA = __half22float2(hA[q]);
                accA[2 * q]     += aA * fA.x;
                accA[2 * q + 1] += aA * fA.y;
            }
            denA += aA;
        }
    }

    float den = denA + denB;
#pragma unroll
    for (int q = 0; q < 8; q++) sred[wid][lane * 8 + q] = accA[q] + accB[q];
    if ((lane & 3) == 0) sden[wid][head] = den;
    __syncthreads();

    int d0 = 2 * t;
    int hh = t >> 4;
    float o0 = (sred[0][d0] + sred[1][d0]) + (sred[2][d0] + sred[3][d0]);
    float o1 = (sred[0][d0 + 1] + sred[1][d0 + 1]) + (sred[2][d0 + 1] + sred[3][d0 + 1]);
    float dsum = (sden[0][hh] + sden[1][hh]) + (sden[2][hh] + sden[3][hh]);
    float inv = (s1 > s0) ? (1.f / dsum) : 0.f;
    o0 = o0 * inv + bias[d0];
    o1 = o1 * inv + bias[d0 + 1];
    o0 = (o0 > 0.f) ? o0 : (__expf(o0) - 1.f);
    o1 = (o1 > 0.f) ? o1 : (__expf(o1) - 1.f);
    *(float2*)(out + (size_t)i * F0DIM + d0) = make_float2(o0, o1);
}

// ---------------------------------------------------------------------------
// Layer-1 aggregation with fused edge weights. Warp per node, lane = dim.
// ---------------------------------------------------------------------------
__global__ void k_agg1(const float* __restrict__ f,
                       const float* __restrict__ el,
                       const float* __restrict__ er,
                       const float* __restrict__ bias,
                       float* __restrict__ out, int N) {
    int w = (blockIdx.x * blockDim.x + threadIdx.x) >> 5;
    int lane = threadIdx.x & 31;
    if (w >= N) return;
    int s0 = g_rowptr[w], s1 = g_rowptr[w + 1];
    float er_i = er[w];
    float accA = 0.f, accB = 0.f, denA = 0.f, denB = 0.f;
    int j = s0;
    for (; j + 1 < s1; j += 2) {
        int sA = g_csrc[j], sB = g_csrc[j + 1];
        float eA = el[sA] + er_i;
        float eB = el[sB] + er_i;
        eA = (eA > 0.f) ? eA : 0.2f * eA;
        eB = (eB > 0.f) ? eB : 0.2f * eB;
        float aA = __expf(eA), aB = __expf(eB);
        accA += aA * f[(size_t)sA * DOUT + lane];
        accB += aB * f[(size_t)sB * DOUT + lane];
        denA += aA; denB += aB;
    }
    if (j < s1) {
        int sA = g_csrc[j];
        float eA = el[sA] + er_i;
        eA = (eA > 0.f) ? eA : 0.2f * eA;
        float aA = __expf(eA);
        accA += aA * f[(size_t)sA * DOUT + lane];
        denA += aA;
    }
    float den = denA + denB;
    float o = (s1 > s0) ? ((accA + accB) / den) : 0.f;
    out[(size_t)w * DOUT + lane] = o + bias[lane];
}

// ---------------------------------------------------------------------------
// Link predictor
// ---------------------------------------------------------------------------
__global__ void k_predictor(const float* __restrict__ h,
                            const int* __restrict__ ratio_ptr,
                            const float* __restrict__ P1, const float* __restrict__ pb1,
                            const float* __restrict__ P2, const float* __restrict__ pb2,
                            const float* __restrict__ P3, const float* __restrict__ pb3,
                            float* __restrict__ out, int N) {
    __shared__ float sP1[32 * 32], sP2[32 * 32], sP3[32], sb1[32], sb2[32];
    __shared__ float sb3;
    int t = threadIdx.x;
    for (int idx = t; idx < 1024; idx += blockDim.x) {
        sP1[idx] = P1[idx];
        sP2[idx] = P2[idx];
    }
    if (t < 32) { sP3[t] = P3[t]; sb1[t] = pb1[t]; sb2[t] = pb2[t]; }
    if (t == 0) sb3 = pb3[0];
    __syncthreads();

    int ratio = *ratio_ptr;
    int ne = N / (ratio + 2);
    int R = (1 + ratio) * ne;
    int lane = t & 31;
    int wpb = blockDim.x >> 5;
    for (int r = blockIdx.x * wpb + (t >> 5); r < R; r += gridDim.x * wpb) {
        int ia, ib, oi;
        if (r < ne) { ia = r; ib = r + ne; oi = r; }
        else {
            int j = r - ne;
            ia = j % ne; ib = 2 * ne + j; oi = ne + j;
        }
        float z = h[(size_t)ia * DOUT + lane] * h[(size_t)ib * DOUT + lane];

        float z1 = sb1[lane];
#pragma unroll
        for (int k = 0; k < 32; k++)
            z1 += __shfl_sync(0xffffffffu, z, k) * sP1[k * 32 + lane];
        z1 = fmaxf(z1, 0.f);

        float z2 = sb2[lane];
#pragma unroll
        for (int k = 0; k < 32; k++)
            z2 += __shfl_sync(0xffffffffu, z1, k) * sP2[k * 32 + lane];
        z2 = fmaxf(z2, 0.f);

        float v = z2 * sP3[lane];
#pragma unroll
        for (int off = 16; off; off >>= 1)
            v += __shfl_down_sync(0xffffffffu, v, off);
        if (lane == 0) out[oi] = v + sb3;
    }
}

// ---------------------------------------------------------------------------
// Launch: R10-proven fork/join (CSR on main stream, gemm0 on side stream).
// Only change vs the 272.7us baseline: agg0 edge loop unrolled x2.
// ---------------------------------------------------------------------------
extern "C" void kernel_launch(void* const* d_in, const int* in_sizes, int n_in,
                              void* d_out, int out_size) {
    const float* x    = (const float*)d_in[0];
    const int*   src  = (const int*)d_in[1];
    const int*   dst  = (const int*)d_in[2];
    const int*   nsr  = (const int*)d_in[3];
    const float* W0   = (const float*)d_in[4];
    const float* al0  = (const float*)d_in[5];
    const float* ar0  = (const float*)d_in[6];
    const float* b0   = (const float*)d_in[7];
    const float* W1   = (const float*)d_in[8];
    const float* al1  = (const float*)d_in[9];
    const float* ar1  = (const float*)d_in[10];
    const float* b1   = (const float*)d_in[11];
    const float* P1   = (const float*)d_in[12];
    const float* pb1  = (const float*)d_in[13];
    const float* P2   = (const float*)d_in[14];
    const float* pb2  = (const float*)d_in[15];
    const float* P3   = (const float*)d_in[16];
    const float* pb3  = (const float*)d_in[17];
    float* out = (float*)d_out;

    int N = in_sizes[0] / 128;
    int E = in_sizes[1];

    __half* p_f16; float *p_h0, *p_f1, *p_h1, *p_el0, *p_er0, *p_el1, *p_er1;
    int* p_cnt;
    cudaGetSymbolAddress((void**)&p_f16, g_f16);
    cudaGetSymbolAddress((void**)&p_h0,  g_h0);
    cudaGetSymbolAddress((void**)&p_f1,  g_f1);
    cudaGetSymbolAddress((void**)&p_h1,  g_h1);
    cudaGetSymbolAddress((void**)&p_el0, g_el0);
    cudaGetSymbolAddress((void**)&p_er0, g_er0);
    cudaGetSymbolAddress((void**)&p_el1, g_el1);
    cudaGetSymbolAddress((void**)&p_er1, g_er1);
    cudaGetSymbolAddress((void**)&p_cnt, g_cnt);

    static cudaStream_t s_side = nullptr;
    static cudaEvent_t  s_evF = nullptr, s_evJ = nullptr;
    if (s_side == nullptr) {
        cudaStreamCreateWithFlags(&s_side, cudaStreamNonBlocking);
        cudaEventCreateWithFlags(&s_evF, cudaEventDisableTiming);
        cudaEventCreateWithFlags(&s_evJ, cudaEventDisableTiming);
    }

    int nbE = (E + 255) / 256;

    // Fork: side stream joins the capture dependency graph here.
    cudaEventRecord(s_evF, 0);
    cudaStreamWaitEvent(s_side, s_evF, 0);

    // Side stream: layer-0 GEMM (independent of the CSR build)
    {
        dim3 grid(F0DIM / 128, (N + 127) / 128);
        k_gemm_tf32<128, 4, 2, true><<<grid, 256, 0, s_side>>>(
            x, W0, p_f16, al0, ar0, p_el0, p_er0, N, F0DIM, 128, H0);
    }

    // Main stream: CSR build
    cudaMemsetAsync(p_cnt, 0, (size_t)N * sizeof(int), 0);
    k_hist<<<nbE, 256>>>(dst, E);
    k_scan<<<1, 1024>>>(N);
    k_fill<<<nbE, 256>>>(src, dst, E);

    // Join: main stream waits for gemm0 before agg0.
    cudaEventRecord(s_evJ, s_side);
    cudaStreamWaitEvent(0, s_evJ, 0);

    // Layer-0 aggregation (fused weights, warp-per-edge x2, +elu)
    k_agg0<<<N, 128>>>(p_f16, p_el0, p_er0, b0, p_h0, N);

    // Layer-1 GEMM -> aggregation (fused weights)
    {
        dim3 grid(DOUT / 32, (N + 127) / 128);
        k_gemm_tf32<32, 8, 1, false><<<grid, 256>>>(p_h0, W1, p_f1, al1, ar1,
                                                    p_el1, p_er1, N, DOUT, F0DIM, 1);
    }
    k_agg1<<<(N * 32 + 255) / 256, 256>>>(p_f1, p_el1, p_er1, b1, p_h1, N);

    // Predictor
    k_predictor<<<512, 256>>>(p_h1, nsr, P1, pb1, P2, pb2, P3, pb3, out, N);
}

// round 15
// speedup vs baseline: 1.1700x; 1.1700x over previous
#include <cuda_runtime.h>
#include <cuda_fp16.h>
#include <cstdint>
#include <cstddef>

// ---------------------------------------------------------------------------
// Problem constants (padded capacities for static scratch)
// ---------------------------------------------------------------------------
#define NMAX 50048
#define EMAX 1000064
#define H0 8
#define DOUT 32
#define F0DIM (H0*DOUT)     // 256

// ---------------------------------------------------------------------------
// Static device scratch
// ---------------------------------------------------------------------------
__device__ __half g_f16[(size_t)NMAX * F0DIM];   // layer-0 features (fp16)
__device__ float g_h0[(size_t)NMAX * F0DIM];     // layer-0 output (after elu)
__device__ float g_f1[(size_t)NMAX * DOUT];
__device__ float g_h1[(size_t)NMAX * DOUT];
__device__ float g_el0[(size_t)NMAX * H0];
__device__ float g_er0[(size_t)NMAX * H0];
__device__ float g_el1[NMAX];
__device__ float g_er1[NMAX];
__device__ int   g_cnt[NMAX];
__device__ int   g_rowptr[NMAX + 1];
__device__ int   g_cursor[NMAX];
__device__ int   g_csrc[EMAX];

// ---------------------------------------------------------------------------
// CSR build: hist -> scan -> fill (+ memset for counts)
// ---------------------------------------------------------------------------
__global__ void k_hist(const int* __restrict__ dst, int E) {
    int e = blockIdx.x * blockDim.x + threadIdx.x;
    if (e < E) atomicAdd(&g_cnt[dst[e]], 1);
}

__global__ void k_scan(int N) {
    __shared__ int s[1024];
    int t = threadIdx.x;
    int C = (N + 1023) / 1024;
    int beg = t * C;
    int end = beg + C; if (end > N) end = N;
    int sum = 0;
    for (int i = beg; i < end; i++) sum += g_cnt[i];
    s[t] = sum;
    __syncthreads();
    for (int off = 1; off < 1024; off <<= 1) {
        int u = (t >= off) ? s[t - off] : 0;
        __syncthreads();
        if (t >= off) s[t] += u;
        __syncthreads();
    }
    int pre = (t == 0) ? 0 : s[t - 1];
    for (int i = beg; i < end; i++) {
        int c = g_cnt[i];
        g_rowptr[i] = pre;
        g_cursor[i] = pre;
        pre += c;
    }
    if (t == 1023) g_rowptr[N] = s[1023];
}

__global__ void k_fill(const int* __restrict__ src, const int* __restrict__ dst, int E) {
    int e = blockIdx.x * blockDim.x + threadIdx.x;
    if (e < E) {
        int p = atomicAdd(&g_cursor[dst[e]], 1);
        g_csrc[p] = src[e];
    }
}

// ---------------------------------------------------------------------------
// TF32 tensor-core GEMM with fused attention-score epilogue.
// ---------------------------------------------------------------------------
__device__ __forceinline__ uint32_t f2tf32(float v) {
    uint32_t u;
    asm("cvt.rna.tf32.f32 %0, %1;" : "=r"(u) : "f"(v));
    return u;
}

template<int BN, int WMI, int WNI, bool HALF_OUT>
__global__ __launch_bounds__(256) void k_gemm_tf32(
    const float* __restrict__ A, const float* __restrict__ B,
    void* __restrict__ Cv,
    const float* __restrict__ al, const float* __restrict__ ar,
    float* __restrict__ el, float* __restrict__ er,
    int M, int N, int K, int H)
{
    constexpr int BM = 128;
    constexpr int BK = 32;
    constexpr int WM = BM / WMI;
    constexpr int WN = BN / WNI;
    constexpr int MFR = WM / 16;
    constexpr int NFR = WN / 8;
    constexpr int HW  = (WN + 31) / 32;
    constexpr int AS_STRIDE = 36;
    constexpr int BS_STRIDE = BN + 8;

    __shared__ uint32_t As[BM * AS_STRIDE];
    __shared__ uint32_t Bs[BK * BS_STRIDE];

    int tid = threadIdx.x;
    int lane = tid & 31;
    int w = tid >> 5;
    int warp_m = w % WMI;
    int warp_n = w / WMI;
    int m0 = blockIdx.y * BM;
    int n0 = blockIdx.x * BN;
    int wr = warp_m * WM;

    float c[MFR][NFR][4];
#pragma unroll
    for (int i = 0; i < MFR; i++)
#pragma unroll
        for (int j = 0; j < NFR; j++)
#pragma unroll
            for (int q = 0; q < 4; q++) c[i][j][q] = 0.f;

    for (int k0 = 0; k0 < K; k0 += BK) {
#pragma unroll
        for (int q = 0; q < (BM * BK / 4) / 256; q++) {
            int idx = tid + q * 256;
            int row = idx >> 3;
            int c4  = idx & 7;
            uint4 u = make_uint4(0u, 0u, 0u, 0u);
            int grow = m0 + row;
            if (grow < M) {
                float4 v = *(const float4*)(A + (size_t)grow * K + k0 + c4 * 4);
                u.x = f2tf32(v.x); u.y = f2tf32(v.y);
                u.z = f2tf32(v.z); u.w = f2tf32(v.w);
            }
            *(uint4*)&As[row * AS_STRIDE + c4 * 4] = u;
        }
#pragma unroll
        for (int q = 0; q < (BK * BN / 4) / 256; q++) {
            int idx = tid + q * 256;
            int row = idx / (BN / 4);
            int c4  = idx % (BN / 4);
            float4 v = *(const float4*)(B + (size_t)(k0 + row) * N + n0 + c4 * 4);
            uint4 u;
            u.x = f2tf32(v.x); u.y = f2tf32(v.y);
            u.z = f2tf32(v.z); u.w = f2tf32(v.w);
            *(uint4*)&Bs[row * BS_STRIDE + c4 * 4] = u;
        }
        __syncthreads();

#pragma unroll
        for (int kk = 0; kk < BK; kk += 8) {
            uint32_t af[MFR][4];
#pragma unroll
            for (int mf = 0; mf < MFR; mf++) {
                int r = wr + mf * 16 + (lane >> 2);
                int kc = kk + (lane & 3);
                af[mf][0] = As[r * AS_STRIDE + kc];
                af[mf][1] = As[(r + 8) * AS_STRIDE + kc];
                af[mf][2] = As[r * AS_STRIDE + kc + 4];
                af[mf][3] = As[(r + 8) * AS_STRIDE + kc + 4];
            }
            uint32_t bf[NFR][2];
#pragma unroll
            for (int nf = 0; nf < NFR; nf++) {
                int n = warp_n * WN + nf * 8 + (lane >> 2);
                int kc = kk + (lane & 3);
                bf[nf][0] = Bs[kc * BS_STRIDE + n];
                bf[nf][1] = Bs[(kc + 4) * BS_STRIDE + n];
            }
#pragma unroll
            for (int mf = 0; mf < MFR; mf++)
#pragma unroll
                for (int nf = 0; nf < NFR; nf++) {
                    asm volatile(
                        "mma.sync.aligned.m16n8k8.row.col.f32.tf32.tf32.f32 "
                        "{%0,%1,%2,%3}, {%4,%5,%6,%7}, {%8,%9}, {%0,%1,%2,%3};\n"
                        : "+f"(c[mf][nf][0]), "+f"(c[mf][nf][1]),
                          "+f"(c[mf][nf][2]), "+f"(c[mf][nf][3])
                        : "r"(af[mf][0]), "r"(af[mf][1]), "r"(af[mf][2]), "r"(af[mf][3]),
                          "r"(bf[nf][0]), "r"(bf[nf][1]));
                }
        }
        __syncthreads();
    }

    float elp[MFR][2][HW], erp[MFR][2][HW];
#pragma unroll
    for (int mf = 0; mf < MFR; mf++)
#pragma unroll
        for (int hf = 0; hf < 2; hf++)
#pragma unroll
            for (int hh = 0; hh < HW; hh++) { elp[mf][hf][hh] = 0.f; erp[mf][hf][hh] = 0.f; }

#pragma unroll
    for (int nf = 0; nf < NFR; nf++) {
        int colb = warp_n * WN + nf * 8;
        int hw = (nf * 8) >> 5;
        int hg = (n0 + colb) >> 5;
        int ch = (colb & 31) + 2 * (lane & 3);
        float av0 = al[hg * 32 + ch], av1 = al[hg * 32 + ch + 1];
        float rv0 = ar[hg * 32 + ch], rv1 = ar[hg * 32 + ch + 1];
        int gcol = n0 + colb + 2 * (lane & 3);
#pragma unroll
        for (int mf = 0; mf < MFR; mf++) {
            int r0 = m0 + wr + mf * 16 + (lane >> 2);
            int r1 = r0 + 8;
            float c0 = c[mf][nf][0], c1 = c[mf][nf][1];
            float c2 = c[mf][nf][2], c3 = c[mf][nf][3];
            if (HALF_OUT) {
                __half* C = (__half*)Cv;
                if (r0 < M) *(__half2*)(C + (size_t)r0 * N + gcol) = __floats2half2_rn(c0, c1);
                if (r1 < M) *(__half2*)(C + (size_t)r1 * N + gcol) = __floats2half2_rn(c2, c3);
            } else {
                float* C = (float*)Cv;
                if (r0 < M) *(float2*)(C + (size_t)r0 * N + gcol) = make_float2(c0, c1);
                if (r1 < M) *(float2*)(C + (size_t)r1 * N + gcol) = make_float2(c2, c3);
            }
            elp[mf][0][hw] += c0 * av0 + c1 * av1;
            elp[mf][1][hw] += c2 * av0 + c3 * av1;
            erp[mf][0][hw] += c0 * rv0 + c1 * rv1;
            erp[mf][1][hw] += c2 * rv0 + c3 * rv1;
        }
    }
#pragma unroll
    for (int mf = 0; mf < MFR; mf++)
#pragma unroll
        for (int hf = 0; hf < 2; hf++)
#pragma unroll
            for (int hh = 0; hh < HW; hh++) {
                float a = elp[mf][hf][hh], b = erp[mf][hf][hh];
                a += __shfl_xor_sync(0xffffffffu, a, 1);
                a += __shfl_xor_sync(0xffffffffu, a, 2);
                b += __shfl_xor_sync(0xffffffffu, b, 1);
                b += __shfl_xor_sync(0xffffffffu, b, 2);
                if ((lane & 3) == 0) {
                    int row = m0 + wr + mf * 16 + (lane >> 2) + hf * 8;
                    int hg = (n0 + warp_n * WN) / 32 + hh;
                    if (row < M) {
                        el[(size_t)row * H + hg] = a;
                        er[(size_t)row * H + hg] = b;
                    }
                }
            }
}

// ---------------------------------------------------------------------------
// Layer-0 aggregation, WARP-PER-NODE: one warp owns all edges of one node.
// Lane covers dims [8*lane, 8*lane+8) via one LDG.128 per edge; weights
// computed inline (head = lane>>2); NO smem, NO barriers, NO reductions.
// ---------------------------------------------------------------------------
__global__ __launch_bounds__(128) void k_agg0(const __half* __restrict__ f16,
                                              const float* __restrict__ el,
                                              const float* __restrict__ er,
                                              const float* __restrict__ bias,
                                              float* __restrict__ out, int N) {
    int i = (blockIdx.x * blockDim.x + threadIdx.x) >> 5;
    int lane = threadIdx.x & 31;
    if (i >= N) return;
    int head = lane >> 2;                      // this lane's head (8 dims/lane)
    int s0 = g_rowptr[i], s1 = g_rowptr[i + 1];
    float er_i = er[i * H0 + head];
    const uint4* frow = (const uint4*)f16;

    float acc[8];
#pragma unroll
    for (int q = 0; q < 8; q++) acc[q] = 0.f;
    float den = 0.f;

    for (int j = s0; j < s1; j++) {
        int s = g_csrc[j];                     // broadcast load
        float e = el[s * H0 + head] + er_i;
        e = (e > 0.f) ? e : 0.2f * e;
        float a = __expf(e);
        uint4 v = frow[(size_t)s * 32 + lane];
        const __half2* hp = (const __half2*)&v;
#pragma unroll
        for (int q = 0; q < 4; q++) {
            float2 f2 = __half22float2(hp[q]);
            acc[2 * q]     += a * f2.x;
            acc[2 * q + 1] += a * f2.y;
        }
        den += a;
    }

    float inv = (s1 > s0) ? (1.f / den) : 0.f;
    int d0 = lane * 8;
    float o[8];
#pragma unroll
    for (int q = 0; q < 8; q++) {
        float v = acc[q] * inv + bias[d0 + q];
        o[q] = (v > 0.f) ? v : (__expf(v) - 1.f);
    }
    float* op = out + (size_t)i * F0DIM + d0;
    *(float4*)op       = make_float4(o[0], o[1], o[2], o[3]);
    *(float4*)(op + 4) = make_float4(o[4], o[5], o[6], o[7]);
}

// ---------------------------------------------------------------------------
// Layer-1 aggregation with fused edge weights. Warp per node, lane = dim.
// ---------------------------------------------------------------------------
__global__ void k_agg1(const float* __restrict__ f,
                       const float* __restrict__ el,
                       const float* __restrict__ er,
                       const float* __restrict__ bias,
                       float* __restrict__ out, int N) {
    int w = (blockIdx.x * blockDim.x + threadIdx.x) >> 5;
    int lane = threadIdx.x & 31;
    if (w >= N) return;
    int s0 = g_rowptr[w], s1 = g_rowptr[w + 1];
    float er_i = er[w];
    float accA = 0.f, accB = 0.f, denA = 0.f, denB = 0.f;
    int j = s0;
    for (; j + 1 < s1; j += 2) {
        int sA = g_csrc[j], sB = g_csrc[j + 1];
        float eA = el[sA] + er_i;
        float eB = el[sB] + er_i;
        eA = (eA > 0.f) ? eA : 0.2f * eA;
        eB = (eB > 0.f) ? eB : 0.2f * eB;
        float aA = __expf(eA), aB = __expf(eB);
        accA += aA * f[(size_t)sA * DOUT + lane];
        accB += aB * f[(size_t)sB * DOUT + lane];
        denA += aA; denB += aB;
    }
    if (j < s1) {
        int sA = g_csrc[j];
        float eA = el[sA] + er_i;
        eA = (eA > 0.f) ? eA : 0.2f * eA;
        float aA = __expf(eA);
        accA += aA * f[(size_t)sA * DOUT + lane];
        denA += aA;
    }
    float den = denA + denB;
    float o = (s1 > s0) ? ((accA + accB) / den) : 0.f;
    out[(size_t)w * DOUT + lane] = o + bias[lane];
}

// ---------------------------------------------------------------------------
// Link predictor
// ---------------------------------------------------------------------------
__global__ void k_predictor(const float* __restrict__ h,
                            const int* __restrict__ ratio_ptr,
                            const float* __restrict__ P1, const float* __restrict__ pb1,
                            const float* __restrict__ P2, const float* __restrict__ pb2,
                            const float* __restrict__ P3, const float* __restrict__ pb3,
                            float* __restrict__ out, int N) {
    __shared__ float sP1[32 * 32], sP2[32 * 32], sP3[32], sb1[32], sb2[32];
    __shared__ float sb3;
    int t = threadIdx.x;
    for (int idx = t; idx < 1024; idx += blockDim.x) {
        sP1[idx] = P1[idx];
        sP2[idx] = P2[idx];
    }
    if (t < 32) { sP3[t] = P3[t]; sb1[t] = pb1[t]; sb2[t] = pb2[t]; }
    if (t == 0) sb3 = pb3[0];
    __syncthreads();

    int ratio = *ratio_ptr;
    int ne = N / (ratio + 2);
    int R = (1 + ratio) * ne;
    int lane = t & 31;
    int wpb = blockDim.x >> 5;
    for (int r = blockIdx.x * wpb + (t >> 5); r < R; r += gridDim.x * wpb) {
        int ia, ib, oi;
        if (r < ne) { ia = r; ib = r + ne; oi = r; }
        else {
            int j = r - ne;
            ia = j % ne; ib = 2 * ne + j; oi = ne + j;
        }
        float z = h[(size_t)ia * DOUT + lane] * h[(size_t)ib * DOUT + lane];

        float z1 = sb1[lane];
#pragma unroll
        for (int k = 0; k < 32; k++)
            z1 += __shfl_sync(0xffffffffu, z, k) * sP1[k * 32 + lane];
        z1 = fmaxf(z1, 0.f);

        float z2 = sb2[lane];
#pragma unroll
        for (int k = 0; k < 32; k++)
            z2 += __shfl_sync(0xffffffffu, z1, k) * sP2[k * 32 + lane];
        z2 = fmaxf(z2, 0.f);

        float v = z2 * sP3[lane];
#pragma unroll
        for (int off = 16; off; off >>= 1)
            v += __shfl_down_sync(0xffffffffu, v, off);
        if (lane == 0) out[oi] = v + sb3;
    }
}

// ---------------------------------------------------------------------------
// Launch: R10-proven fork/join (CSR on main stream, gemm0 on side stream).
// Only change vs the 272.7us baseline: agg0 is warp-per-node, sync-free.
// ---------------------------------------------------------------------------
extern "C" void kernel_launch(void* const* d_in, const int* in_sizes, int n_in,
                              void* d_out, int out_size) {
    const float* x    = (const float*)d_in[0];
    const int*   src  = (const int*)d_in[1];
    const int*   dst  = (const int*)d_in[2];
    const int*   nsr  = (const int*)d_in[3];
    const float* W0   = (const float*)d_in[4];
    const float* al0  = (const float*)d_in[5];
    const float* ar0  = (const float*)d_in[6];
    const float* b0   = (const float*)d_in[7];
    const float* W1   = (const float*)d_in[8];
    const float* al1  = (const float*)d_in[9];
    const float* ar1  = (const float*)d_in[10];
    const float* b1   = (const float*)d_in[11];
    const float* P1   = (const float*)d_in[12];
    const float* pb1  = (const float*)d_in[13];
    const float* P2   = (const float*)d_in[14];
    const float* pb2  = (const float*)d_in[15];
    const float* P3   = (const float*)d_in[16];
    const float* pb3  = (const float*)d_in[17];
    float* out = (float*)d_out;

    int N = in_sizes[0] / 128;
    int E = in_sizes[1];

    __half* p_f16; float *p_h0, *p_f1, *p_h1, *p_el0, *p_er0, *p_el1, *p_er1;
    int* p_cnt;
    cudaGetSymbolAddress((void**)&p_f16, g_f16);
    cudaGetSymbolAddress((void**)&p_h0,  g_h0);
    cudaGetSymbolAddress((void**)&p_f1,  g_f1);
    cudaGetSymbolAddress((void**)&p_h1,  g_h1);
    cudaGetSymbolAddress((void**)&p_el0, g_el0);
    cudaGetSymbolAddress((void**)&p_er0, g_er0);
    cudaGetSymbolAddress((void**)&p_el1, g_el1);
    cudaGetSymbolAddress((void**)&p_er1, g_er1);
    cudaGetSymbolAddress((void**)&p_cnt, g_cnt);

    static cudaStream_t s_side = nullptr;
    static cudaEvent_t  s_evF = nullptr, s_evJ = nullptr;
    if (s_side == nullptr) {
        cudaStreamCreateWithFlags(&s_side, cudaStreamNonBlocking);
        cudaEventCreateWithFlags(&s_evF, cudaEventDisableTiming);
        cudaEventCreateWithFlags(&s_evJ, cudaEventDisableTiming);
    }

    int nbE = (E + 255) / 256;

    // Fork: side stream joins the capture dependency graph here.
    cudaEventRecord(s_evF, 0);
    cudaStreamWaitEvent(s_side, s_evF, 0);

    // Side stream: layer-0 GEMM (independent of the CSR build)
    {
        dim3 grid(F0DIM / 128, (N + 127) / 128);
        k_gemm_tf32<128, 4, 2, true><<<grid, 256, 0, s_side>>>(
            x, W0, p_f16, al0, ar0, p_el0, p_er0, N, F0DIM, 128, H0);
    }

    // Main stream: CSR build
    cudaMemsetAsync(p_cnt, 0, (size_t)N * sizeof(int), 0);
    k_hist<<<nbE, 256>>>(dst, E);
    k_scan<<<1, 1024>>>(N);
    k_fill<<<nbE, 256>>>(src, dst, E);

    // Join: main stream waits for gemm0 before agg0.
    cudaEventRecord(s_evJ, s_side);
    cudaStreamWaitEvent(0, s_evJ, 0);

    // Layer-0 aggregation (warp-per-node, sync-free, +elu)
    k_agg0<<<(N * 32 + 127) / 128, 128>>>(p_f16, p_el0, p_er0, b0, p_h0, N);

    // Layer-1 GEMM -> aggregation (fused weights)
    {
        dim3 grid(DOUT / 32, (N + 127) / 128);
        k_gemm_tf32<32, 8, 1, false><<<grid, 256>>>(p_h0, W1, p_f1, al1, ar1,
                                                    p_el1, p_er1, N, DOUT, F0DIM, 1);
    }
    k_agg1<<<(N * 32 + 255) / 256, 256>>>(p_f1, p_el1, p_er1, b1, p_h1, N);

    // Predictor
    k_predictor<<<512, 256>>>(p_h1, nsr, P1, pb1, P2, pb2, P3, pb3, out, N);
}